// round 1
// baseline (speedup 1.0000x reference)
#include <cuda_runtime.h>
#include <math.h>

#define DIMC   1024
#define HEADS  16
#define HD     64
#define MLPH   716
#define F1N    (3*DIMC + MLPH)   /* 3788 */
#define BATCH  4
#define SEQ    1024
#define TOK    (BATCH*SEQ)       /* 4096 */
#define BH     (BATCH*HEADS)     /* 64 */

/* ---------------- scratch (allocation-free: __device__ globals) ------------ */
__device__ float g_normx[TOK*DIMC];
__device__ float g_f1[(size_t)TOK*F1N];
__device__ float g_q[(size_t)BH*SEQ*HD];
__device__ float g_k[(size_t)BH*SEQ*HD];
__device__ float g_v[(size_t)BH*SEQ*HD];
__device__ float g_attn[(size_t)BH*SEQ*SEQ];   /* 256 MB */
__device__ float g_xo[TOK*DIMC];
__device__ float g_gelu[(size_t)TOK*MLPH];
__device__ float g_comb[(size_t)TOK*2*DIMC];

/* ---------------- reductions ------------------------------------------------ */
__device__ __forceinline__ float blockReduceSum(float val) {
    __shared__ float sh[32];
    int lane = threadIdx.x & 31, wid = threadIdx.x >> 5;
    #pragma unroll
    for (int o = 16; o > 0; o >>= 1) val += __shfl_down_sync(0xffffffffu, val, o);
    if (lane == 0) sh[wid] = val;
    __syncthreads();
    int nw = blockDim.x >> 5;
    val = (threadIdx.x < nw) ? sh[threadIdx.x] : 0.f;
    if (wid == 0) {
        #pragma unroll
        for (int o = 16; o > 0; o >>= 1) val += __shfl_down_sync(0xffffffffu, val, o);
        if (lane == 0) sh[0] = val;
    }
    __syncthreads();
    float r = sh[0];
    __syncthreads();
    return r;
}

__device__ __forceinline__ float blockReduceMax(float val) {
    __shared__ float sh[32];
    int lane = threadIdx.x & 31, wid = threadIdx.x >> 5;
    #pragma unroll
    for (int o = 16; o > 0; o >>= 1) val = fmaxf(val, __shfl_down_sync(0xffffffffu, val, o));
    if (lane == 0) sh[wid] = val;
    __syncthreads();
    int nw = blockDim.x >> 5;
    val = (threadIdx.x < nw) ? sh[threadIdx.x] : -3.0e38f;
    if (wid == 0) {
        #pragma unroll
        for (int o = 16; o > 0; o >>= 1) val = fmaxf(val, __shfl_down_sync(0xffffffffu, val, o));
        if (lane == 0) sh[0] = val;
    }
    __syncthreads();
    float r = sh[0];
    __syncthreads();
    return r;
}

/* ---------------- 1. LayerNorm over DIM ------------------------------------ */
__global__ void ln_rows(const float* __restrict__ x, const float* __restrict__ g,
                        const float* __restrict__ b) {
    int row = blockIdx.x, t = threadIdx.x;
    const float* xr = x + (size_t)row * DIMC;
    float v[4]; float s = 0.f;
    #pragma unroll
    for (int i = 0; i < 4; i++) { v[i] = xr[i*256 + t]; s += v[i]; }
    float mean = blockReduceSum(s) * (1.f/DIMC);
    float s2 = 0.f;
    #pragma unroll
    for (int i = 0; i < 4; i++) { float d = v[i]-mean; s2 += d*d; }
    float var = blockReduceSum(s2) * (1.f/DIMC);
    float inv = rsqrtf(var + 1e-5f);
    float* orow = g_normx + (size_t)row * DIMC;
    #pragma unroll
    for (int i = 0; i < 4; i++) {
        int c = i*256 + t;
        orow[c] = (v[i]-mean)*inv*g[c] + b[c];
    }
}

/* ---------------- generic 128x128x8 SGEMM ----------------------------------
   C[m,n] (ldc) = epilogue(A[MxK] @ B[KxN] + bias)
   EPI==0: C = acc + bias
   EPI==1: C = resid[m*N+n] + (acc + bias[n]) * ls[n]    (residual+layerscale) */
template<int EPI>
__global__ __launch_bounds__(256) void sgemm(
        const float* __restrict__ A, const float* __restrict__ B,
        float* __restrict__ C, int M, int N, int K,
        const float* __restrict__ bias,
        const float* __restrict__ resid, const float* __restrict__ ls, int ldc) {
    __shared__ float As[8][128];
    __shared__ float Bs[8][132];
    int bm = blockIdx.y * 128, bn = blockIdx.x * 128;
    int t = threadIdx.x;
    int tx = t & 15, ty = t >> 4;
    float acc[8][8] = {};
    int am = t >> 1, ak = (t & 1) * 4;
    int bk = t >> 5, bn0 = (t & 31) * 4;

    for (int k0 = 0; k0 < K; k0 += 8) {
        #pragma unroll
        for (int i = 0; i < 4; i++) {
            int kk = ak + i;
            As[kk][am] = (k0 + kk < K) ? A[(size_t)(bm+am)*K + k0 + kk] : 0.f;
        }
        #pragma unroll
        for (int i = 0; i < 4; i++) {
            int n = bn0 + i;
            float val = 0.f;
            if (k0 + bk < K && bn + n < N) val = B[(size_t)(k0+bk)*N + bn + n];
            Bs[bk][n] = val;
        }
        __syncthreads();
        #pragma unroll
        for (int kk = 0; kk < 8; kk++) {
            float a[8], bb[8];
            #pragma unroll
            for (int i = 0; i < 8; i++) a[i]  = As[kk][ty*8 + i];
            #pragma unroll
            for (int j = 0; j < 8; j++) bb[j] = Bs[kk][tx*8 + j];
            #pragma unroll
            for (int i = 0; i < 8; i++)
                #pragma unroll
                for (int j = 0; j < 8; j++)
                    acc[i][j] += a[i] * bb[j];
        }
        __syncthreads();
    }

    #pragma unroll
    for (int i = 0; i < 8; i++) {
        int m = bm + ty*8 + i;
        #pragma unroll
        for (int j = 0; j < 8; j++) {
            int n = bn + tx*8 + j;
            if (n < N) {
                float v = acc[i][j] + (bias ? bias[n] : 0.f);
                if (EPI == 1)
                    C[(size_t)m*ldc + n] = resid[(size_t)m*N + n] + v * ls[n];
                else
                    C[(size_t)m*ldc + n] = v;
            }
        }
    }
}

/* ---------------- 3. split q/k/v + per-head LN on q,k ---------------------- */
__global__ void qkv_split_norm(const float* __restrict__ qg, const float* __restrict__ qb,
                               const float* __restrict__ kg, const float* __restrict__ kb) {
    int w = blockIdx.x * (blockDim.x >> 5) + (threadIdx.x >> 5);
    int lane = threadIdx.x & 31;
    int tkn = w >> 4;            /* token 0..4095 */
    int h   = w & 15;
    int b = tkn >> 10, n = tkn & 1023;
    const float* row = g_f1 + (size_t)tkn * F1N;
    size_t obase = ((size_t)(b*HEADS + h) * SEQ + n) * HD;
    int d0 = lane*2, d1 = d0 + 1;

    /* q */
    {
        float v0 = row[h*HD + d0], v1 = row[h*HD + d1];
        float s = v0 + v1;
        #pragma unroll
        for (int o = 16; o > 0; o >>= 1) s += __shfl_xor_sync(0xffffffffu, s, o);
        float m = s * (1.f/HD);
        float e0 = v0 - m, e1 = v1 - m;
        float s2 = e0*e0 + e1*e1;
        #pragma unroll
        for (int o = 16; o > 0; o >>= 1) s2 += __shfl_xor_sync(0xffffffffu, s2, o);
        float inv = rsqrtf(s2 * (1.f/HD) + 1e-5f);
        g_q[obase + d0] = e0*inv*qg[d0] + qb[d0];
        g_q[obase + d1] = e1*inv*qg[d1] + qb[d1];
    }
    /* k */
    {
        float v0 = row[DIMC + h*HD + d0], v1 = row[DIMC + h*HD + d1];
        float s = v0 + v1;
        #pragma unroll
        for (int o = 16; o > 0; o >>= 1) s += __shfl_xor_sync(0xffffffffu, s, o);
        float m = s * (1.f/HD);
        float e0 = v0 - m, e1 = v1 - m;
        float s2 = e0*e0 + e1*e1;
        #pragma unroll
        for (int o = 16; o > 0; o >>= 1) s2 += __shfl_xor_sync(0xffffffffu, s2, o);
        float inv = rsqrtf(s2 * (1.f/HD) + 1e-5f);
        g_k[obase + d0] = e0*inv*kg[d0] + kb[d0];
        g_k[obase + d1] = e1*inv*kg[d1] + kb[d1];
    }
    /* v copy */
    g_v[obase + d0] = row[2*DIMC + h*HD + d0];
    g_v[obase + d1] = row[2*DIMC + h*HD + d1];
}

/* ---------------- 4. attention scores S = scale * q @ k^T ------------------ */
__global__ __launch_bounds__(256) void attn_scores() {
    __shared__ float qs[64][65];
    __shared__ float ks[64][65];
    int bh = blockIdx.z;
    int qt = blockIdx.y * 64, kt = blockIdx.x * 64;
    int t = threadIdx.x, tx = t & 15, ty = t >> 4;
    const float* qp = g_q + ((size_t)bh*SEQ + qt) * HD;
    const float* kp = g_k + ((size_t)bh*SEQ + kt) * HD;
    #pragma unroll
    for (int i = 0; i < 16; i++) {
        int e = i*256 + t; int r = e >> 6, c = e & 63;
        qs[r][c] = qp[(size_t)r*HD + c];
        ks[r][c] = kp[(size_t)r*HD + c];
    }
    __syncthreads();
    float acc[4][4] = {};
    #pragma unroll 8
    for (int d = 0; d < 64; d++) {
        float a[4], bv[4];
        #pragma unroll
        for (int i = 0; i < 4; i++) a[i]  = qs[ty*4 + i][d];
        #pragma unroll
        for (int j = 0; j < 4; j++) bv[j] = ks[tx*4 + j][d];
        #pragma unroll
        for (int i = 0; i < 4; i++)
            #pragma unroll
            for (int j = 0; j < 4; j++)
                acc[i][j] += a[i] * bv[j];
    }
    const float scale = 0.125f;  /* 64^-0.5 */
    float* S = g_attn + ((size_t)bh*SEQ + qt) * SEQ + kt;
    #pragma unroll
    for (int i = 0; i < 4; i++)
        #pragma unroll
        for (int j = 0; j < 4; j++)
            S[(size_t)(ty*4 + i)*SEQ + tx*4 + j] = acc[i][j] * scale;
}

/* ---------------- 5. softmax over rows of g_attn --------------------------- */
__global__ void softmax_rows() {
    size_t row = blockIdx.x;
    float* p = g_attn + row * SEQ;
    int t = threadIdx.x;
    float v[4]; float mx = -3.0e38f;
    #pragma unroll
    for (int i = 0; i < 4; i++) { v[i] = p[i*256 + t]; mx = fmaxf(mx, v[i]); }
    mx = blockReduceMax(mx);
    float s = 0.f;
    #pragma unroll
    for (int i = 0; i < 4; i++) { v[i] = __expf(v[i] - mx); s += v[i]; }
    s = blockReduceSum(s);
    float inv = 1.f / s;
    #pragma unroll
    for (int i = 0; i < 4; i++) p[i*256 + t] = v[i] * inv;
}

/* ---------------- 6. xo = attn @ v, written token-major -------------------- */
__global__ __launch_bounds__(256) void attn_v() {
    __shared__ float As[64][17];
    __shared__ float Vs[16][65];
    int bh = blockIdx.y;
    int qt = blockIdx.x * 64;
    int t = threadIdx.x, tx = t & 15, ty = t >> 4;
    const float* Abase = g_attn + ((size_t)bh*SEQ + qt) * SEQ;
    const float* Vbase = g_v + (size_t)bh*SEQ*HD;
    float acc[4][4] = {};
    for (int k0 = 0; k0 < SEQ; k0 += 16) {
        #pragma unroll
        for (int i = 0; i < 4; i++) {
            int e = i*256 + t; int r = e >> 4, c = e & 15;
            As[r][c] = Abase[(size_t)r*SEQ + k0 + c];
        }
        #pragma unroll
        for (int i = 0; i < 4; i++) {
            int e = i*256 + t; int r = e >> 6, c = e & 63;
            Vs[r][c] = Vbase[(size_t)(k0 + r)*HD + c];
        }
        __syncthreads();
        #pragma unroll
        for (int kk = 0; kk < 16; kk++) {
            float a[4], bv[4];
            #pragma unroll
            for (int i = 0; i < 4; i++) a[i]  = As[ty*4 + i][kk];
            #pragma unroll
            for (int j = 0; j < 4; j++) bv[j] = Vs[kk][tx*4 + j];
            #pragma unroll
            for (int i = 0; i < 4; i++)
                #pragma unroll
                for (int j = 0; j < 4; j++)
                    acc[i][j] += a[i] * bv[j];
        }
        __syncthreads();
    }
    int b_ = bh >> 4, h = bh & 15;
    #pragma unroll
    for (int i = 0; i < 4; i++) {
        int token = b_*SEQ + qt + ty*4 + i;
        #pragma unroll
        for (int j = 0; j < 4; j++)
            g_xo[(size_t)token*DIMC + h*HD + tx*4 + j] = acc[i][j];
    }
}

/* ---------------- 7. exact GELU on mlp hidden ------------------------------ */
__global__ void gelu_k() {
    size_t i = (size_t)blockIdx.x * 256 + threadIdx.x;
    if (i < (size_t)TOK * MLPH) {
        size_t r = i / MLPH, c = i % MLPH;
        float x = g_f1[r*F1N + 3*DIMC + c];
        g_gelu[i] = 0.5f * x * (1.f + erff(x * 0.70710678118654752f));
    }
}

/* ---------------- launcher -------------------------------------------------- */
extern "C" void kernel_launch(void* const* d_in, const int* in_sizes, int n_in,
                              void* d_out, int out_size) {
    const float* x      = (const float*)d_in[0];
    const float* norm_g = (const float*)d_in[1];
    const float* norm_b = (const float*)d_in[2];
    const float* W1     = (const float*)d_in[3];
    const float* b1     = (const float*)d_in[4];
    const float* qn_g   = (const float*)d_in[5];
    const float* qn_b   = (const float*)d_in[6];
    const float* kn_g   = (const float*)d_in[7];
    const float* kn_b   = (const float*)d_in[8];
    const float* projW  = (const float*)d_in[9];
    const float* projb  = (const float*)d_in[10];
    const float* mlpW   = (const float*)d_in[11];
    const float* W2     = (const float*)d_in[12];
    const float* b2     = (const float*)d_in[13];
    const float* ls_g   = (const float*)d_in[14];
    float* out = (float*)d_out;

    float *p_normx, *p_f1, *p_xo, *p_gelu, *p_comb;
    cudaGetSymbolAddress((void**)&p_normx, g_normx);
    cudaGetSymbolAddress((void**)&p_f1,    g_f1);
    cudaGetSymbolAddress((void**)&p_xo,    g_xo);
    cudaGetSymbolAddress((void**)&p_gelu,  g_gelu);
    cudaGetSymbolAddress((void**)&p_comb,  g_comb);

    /* 1. layernorm */
    ln_rows<<<TOK, 256>>>(x, norm_g, norm_b);

    /* 2. f1 = normx @ W1 + b1   [4096 x 3788 x 1024] */
    sgemm<0><<<dim3((F1N+127)/128, TOK/128), 256>>>(
        p_normx, W1, p_f1, TOK, F1N, DIMC, b1, nullptr, nullptr, F1N);

    /* 3. split + qk layernorm */
    qkv_split_norm<<<TOK*HEADS/8, 256>>>(qn_g, qn_b, kn_g, kn_b);

    /* 4-6. attention */
    attn_scores<<<dim3(SEQ/64, SEQ/64, BH), 256>>>();
    softmax_rows<<<BH*SEQ, 256>>>();
    attn_v<<<dim3(SEQ/64, BH), 256>>>();

    /* 7. gelu */
    gelu_k<<<(int)(((size_t)TOK*MLPH + 255)/256), 256>>>();

    /* 8. attn_out = xo @ projW + projb -> comb[:, :1024] (ldc=2048) */
    sgemm<0><<<dim3(DIMC/128, TOK/128), 256>>>(
        p_xo, projW, p_comb, TOK, DIMC, DIMC, projb, nullptr, nullptr, 2*DIMC);

    /* 9. mlp_out = gelu @ mlpW -> comb[:, 1024:2048] */
    sgemm<0><<<dim3(DIMC/128, TOK/128), 256>>>(
        p_gelu, mlpW, p_comb + DIMC, TOK, DIMC, MLPH, nullptr, nullptr, nullptr, 2*DIMC);

    /* 10. out = x + (comb @ W2 + b2) * ls_g */
    sgemm<1><<<dim3(DIMC/128, TOK/128), 256>>>(
        p_comb, W2, out, TOK, DIMC, 2*DIMC, b2, x, ls_g, DIMC);
}

// round 3
// speedup vs baseline: 4.3729x; 4.3729x over previous
#include <cuda_runtime.h>
#include <cuda_bf16.h>
#include <math.h>
#include <stdint.h>

#define DIMC   1024
#define HEADS  16
#define HD     64
#define MLPH   716
#define F1N    3788
#define F1NP   3840              /* padded 3788 -> 3840 */
#define MLPKP  736               /* padded 716 -> 736   */
#define BATCH  4
#define SEQ    1024
#define TOK    (BATCH*SEQ)       /* 4096 */
#define BH     (BATCH*HEADS)     /* 64 */

typedef __nv_bfloat16 bf16;

/* ---------------- single scratch arena ------------------------------------- */
#define SZ_NORMX ((size_t)TOK*DIMC*2)
#define SZ_W1B   ((size_t)DIMC*F1NP*2)
#define SZ_PROJW ((size_t)DIMC*DIMC*2)
#define SZ_MLPW  ((size_t)MLPKP*DIMC*2)
#define SZ_W2B   ((size_t)2*DIMC*DIMC*2)
#define SZ_F1    ((size_t)TOK*F1NP*4)
#define SZ_QKV   ((size_t)BH*SEQ*HD*2)
#define SZ_ATTN  ((size_t)BH*SEQ*SEQ*2)
#define SZ_XO    ((size_t)TOK*DIMC*2)
#define SZ_GELU  ((size_t)TOK*MLPKP*2)
#define SZ_COMB  ((size_t)TOK*2*DIMC*2)

#define OF_NORMX ((size_t)0)
#define OF_W1B   (OF_NORMX + SZ_NORMX)
#define OF_PROJW (OF_W1B   + SZ_W1B)
#define OF_MLPW  (OF_PROJW + SZ_PROJW)
#define OF_W2B   (OF_MLPW  + SZ_MLPW)
#define OF_F1    (OF_W2B   + SZ_W2B)
#define OF_Q     (OF_F1    + SZ_F1)
#define OF_K     (OF_Q     + SZ_QKV)
#define OF_V     (OF_K     + SZ_QKV)
#define OF_ATTN  (OF_V     + SZ_QKV)
#define OF_XO    (OF_ATTN  + SZ_ATTN)
#define OF_GELU  (OF_XO    + SZ_XO)
#define OF_COMB  (OF_GELU  + SZ_GELU)
#define OF_END   (OF_COMB  + SZ_COMB)

__device__ __align__(256) unsigned char g_scratch[OF_END];

/* ---------------- PTX helpers ---------------------------------------------- */
__device__ __forceinline__ uint32_t smem_u32(const void* p) {
    return (uint32_t)__cvta_generic_to_shared(p);
}
__device__ __forceinline__ void cp16(uint32_t dst, const void* src) {
    asm volatile("cp.async.cg.shared.global [%0], [%1], 16;\n" :: "r"(dst), "l"(src));
}
__device__ __forceinline__ void cp_commit() { asm volatile("cp.async.commit_group;\n"); }
__device__ __forceinline__ void cp_wait1()  { asm volatile("cp.async.wait_group 1;\n"); }
__device__ __forceinline__ void ldm_x4(uint32_t& r0, uint32_t& r1, uint32_t& r2, uint32_t& r3, uint32_t a) {
    asm volatile("ldmatrix.sync.aligned.m8n8.x4.shared.b16 {%0,%1,%2,%3}, [%4];\n"
                 : "=r"(r0), "=r"(r1), "=r"(r2), "=r"(r3) : "r"(a));
}
__device__ __forceinline__ void ldm_x2(uint32_t& r0, uint32_t& r1, uint32_t a) {
    asm volatile("ldmatrix.sync.aligned.m8n8.x2.shared.b16 {%0,%1}, [%2];\n"
                 : "=r"(r0), "=r"(r1) : "r"(a));
}
__device__ __forceinline__ void ldm_x2_t(uint32_t& r0, uint32_t& r1, uint32_t a) {
    asm volatile("ldmatrix.sync.aligned.m8n8.x2.trans.shared.b16 {%0,%1}, [%2];\n"
                 : "=r"(r0), "=r"(r1) : "r"(a));
}
__device__ __forceinline__ void mma16816(float* c, const uint32_t* a, const uint32_t* b) {
    asm volatile("mma.sync.aligned.m16n8k16.row.col.f32.bf16.bf16.f32 "
                 "{%0,%1,%2,%3}, {%4,%5,%6,%7}, {%8,%9}, {%0,%1,%2,%3};\n"
                 : "+f"(c[0]), "+f"(c[1]), "+f"(c[2]), "+f"(c[3])
                 : "r"(a[0]), "r"(a[1]), "r"(a[2]), "r"(a[3]), "r"(b[0]), "r"(b[1]));
}

/* ---------------- tile prefetch (no lambda) -------------------------------- */
template<int BTRANS, int NTILE>
__device__ __forceinline__ void tile_prefetch(
        const bf16* __restrict__ A, const bf16* __restrict__ B,
        bf16* As, bf16* Bs, int k0, int bm, int bn, int lda, int ldb, int t) {
    const int ar = t >> 1;
    const int ac = (t & 1) * 16;
    uint32_t ad = smem_u32(As + ar * 40 + ac);
    const bf16* asrc = A + (size_t)(bm + ar) * lda + k0 + ac;
    cp16(ad, asrc);
    cp16(ad + 16, asrc + 8);
    if (BTRANS) {
        const int BSS = NTILE + 8;
        if (NTILE == 128) {
            int br = t >> 3, bc = (t & 7) * 16;
            uint32_t bd = smem_u32(Bs + br * BSS + bc);
            const bf16* bsrc = B + (size_t)(k0 + br) * ldb + bn + bc;
            cp16(bd, bsrc);
            cp16(bd + 16, bsrc + 8);
        } else {
            int br = t >> 3, bc = (t & 7) * 8;
            uint32_t bd = smem_u32(Bs + br * BSS + bc);
            const bf16* bsrc = B + (size_t)(k0 + br) * ldb + bn + bc;
            cp16(bd, bsrc);
        }
    } else {
        int br = t >> 1, bc = (t & 1) * 16;
        uint32_t bd = smem_u32(Bs + br * 40 + bc);
        const bf16* bsrc = B + (size_t)(bn + br) * ldb + k0 + bc;
        cp16(bd, bsrc);
        cp16(bd + 16, bsrc + 8);
    }
}

/* ---------------- generic bf16 HMMA GEMM -----------------------------------
   BTRANS=1: B row-major [K,N].  BTRANS=0: B is [N,K] row-major (= B^T).
   EPI 0: float C = acc + bias
   EPI 1: bf16  C = acc*scale + bias
   EPI 2: float C = resid + (acc+bias)*ls                                     */
template<int EPI, int BTRANS, int NTILE>
__global__ __launch_bounds__(256) void hgemm(
        const bf16* __restrict__ A, const bf16* __restrict__ B, void* __restrict__ Cv,
        int K, int lda, int ldb, int ldc,
        size_t strideA, size_t strideB, size_t strideC1, size_t strideC2, int cdiv,
        const float* __restrict__ bias, int nbias,
        const float* __restrict__ resid, const float* __restrict__ ls, float scale) {
    const int WARPS_M = (NTILE == 128) ? 2 : 4;
    const int WARPS_N = 8 / WARPS_M;
    const int WTM = 128 / WARPS_M;              /* 64 or 32 */
    const int MT  = WTM / 16;                   /* 4 or 2   */
    const int BSS = NTILE + 8;
    const int BS_ELEMS = BTRANS ? (32 * (NTILE + 8)) : (NTILE * 40);

    __shared__ __align__(16) bf16 As[2][128 * 40];
    __shared__ __align__(16) bf16 Bs[2][(BTRANS ? (32 * (NTILE + 8)) : (NTILE * 40))];
    (void)BS_ELEMS;

    const int t = threadIdx.x;
    const int lane = t & 31;
    const int warp = t >> 5;
    const int bm = blockIdx.y * 128;
    const int bn = blockIdx.x * NTILE;
    const int z  = blockIdx.z;
    const int wm = (warp / WARPS_N) * WTM;
    const int wn = (warp % WARPS_N) * 32;

    const bf16* Az = A + (size_t)z * strideA;
    const bf16* Bz = B + (size_t)z * strideB;
    const size_t coff = (size_t)(z / cdiv) * strideC1 + (size_t)(z % cdiv) * strideC2;

    float acc[(NTILE == 128) ? 4 : 2][4][4];
    #pragma unroll
    for (int i = 0; i < MT; i++)
        #pragma unroll
        for (int j = 0; j < 4; j++)
            #pragma unroll
            for (int e = 0; e < 4; e++) acc[i][j][e] = 0.f;

    const int KT = K / 32;

    tile_prefetch<BTRANS, NTILE>(Az, Bz, &As[0][0], &Bs[0][0], 0, bm, bn, lda, ldb, t);
    cp_commit();

    int s = 0;
    for (int kt = 0; kt < KT; kt++) {
        if (kt + 1 < KT)
            tile_prefetch<BTRANS, NTILE>(Az, Bz, &As[s ^ 1][0], &Bs[s ^ 1][0],
                                         (kt + 1) * 32, bm, bn, lda, ldb, t);
        cp_commit();
        cp_wait1();
        __syncthreads();

        #pragma unroll
        for (int kk = 0; kk < 2; kk++) {
            uint32_t afr[(NTILE == 128) ? 4 : 2][4];
            #pragma unroll
            for (int i = 0; i < MT; i++) {
                uint32_t a = smem_u32(&As[s][(wm + i * 16 + (lane & 15)) * 40 + kk * 16 + (lane >> 4) * 8]);
                ldm_x4(afr[i][0], afr[i][1], afr[i][2], afr[i][3], a);
            }
            uint32_t bfr[4][2];
            #pragma unroll
            for (int j = 0; j < 4; j++) {
                if (BTRANS) {
                    uint32_t a = smem_u32(&Bs[s][(kk * 16 + (lane & 15)) * BSS + wn + j * 8]);
                    ldm_x2_t(bfr[j][0], bfr[j][1], a);
                } else {
                    uint32_t a = smem_u32(&Bs[s][(wn + j * 8 + (lane & 7)) * 40 + kk * 16 + ((lane >> 3) & 1) * 8]);
                    ldm_x2(bfr[j][0], bfr[j][1], a);
                }
            }
            #pragma unroll
            for (int i = 0; i < MT; i++)
                #pragma unroll
                for (int j = 0; j < 4; j++)
                    mma16816(acc[i][j], afr[i], bfr[j]);
        }
        __syncthreads();
        s ^= 1;
    }

    #pragma unroll
    for (int i = 0; i < MT; i++) {
        int m0 = bm + wm + i * 16 + (lane >> 2);
        #pragma unroll
        for (int j = 0; j < 4; j++) {
            int n0 = bn + wn + j * 8 + (lane & 3) * 2;
            #pragma unroll
            for (int e = 0; e < 4; e++) {
                int m = m0 + (e >> 1) * 8;
                int n = n0 + (e & 1);
                float v = acc[i][j][e] * scale;
                float bv = (bias != 0 && n < nbias) ? bias[n] : 0.f;
                if (EPI == 0) {
                    ((float*)Cv)[coff + (size_t)m * ldc + n] = v + bv;
                } else if (EPI == 1) {
                    ((bf16*)Cv)[coff + (size_t)m * ldc + n] = __float2bfloat16(v + bv);
                } else {
                    ((float*)Cv)[coff + (size_t)m * ldc + n] =
                        resid[(size_t)m * ldc + n] + (v + bv) * ls[n];
                }
            }
        }
    }
}

/* ---------------- reductions ------------------------------------------------ */
__device__ __forceinline__ float blockReduceSum(float val) {
    __shared__ float sh[32];
    int lane = threadIdx.x & 31, wid = threadIdx.x >> 5;
    #pragma unroll
    for (int o = 16; o > 0; o >>= 1) val += __shfl_down_sync(0xffffffffu, val, o);
    if (lane == 0) sh[wid] = val;
    __syncthreads();
    val = (threadIdx.x < (blockDim.x >> 5)) ? sh[threadIdx.x] : 0.f;
    if (wid == 0) {
        #pragma unroll
        for (int o = 16; o > 0; o >>= 1) val += __shfl_down_sync(0xffffffffu, val, o);
        if (lane == 0) sh[0] = val;
    }
    __syncthreads();
    float r = sh[0];
    __syncthreads();
    return r;
}
__device__ __forceinline__ float blockReduceMax(float val) {
    __shared__ float sh[32];
    int lane = threadIdx.x & 31, wid = threadIdx.x >> 5;
    #pragma unroll
    for (int o = 16; o > 0; o >>= 1) val = fmaxf(val, __shfl_down_sync(0xffffffffu, val, o));
    if (lane == 0) sh[wid] = val;
    __syncthreads();
    val = (threadIdx.x < (blockDim.x >> 5)) ? sh[threadIdx.x] : -3.0e38f;
    if (wid == 0) {
        #pragma unroll
        for (int o = 16; o > 0; o >>= 1) val = fmaxf(val, __shfl_down_sync(0xffffffffu, val, o));
        if (lane == 0) sh[0] = val;
    }
    __syncthreads();
    float r = sh[0];
    __syncthreads();
    return r;
}

/* ---------------- LayerNorm -> bf16 ---------------------------------------- */
__global__ void ln_rows(const float* __restrict__ x, const float* __restrict__ g,
                        const float* __restrict__ b, bf16* __restrict__ outb) {
    int row = blockIdx.x, t = threadIdx.x;
    const float* xr = x + (size_t)row * DIMC;
    float v[4]; float s = 0.f;
    #pragma unroll
    for (int i = 0; i < 4; i++) { v[i] = xr[i * 256 + t]; s += v[i]; }
    float mean = blockReduceSum(s) * (1.f / DIMC);
    float s2 = 0.f;
    #pragma unroll
    for (int i = 0; i < 4; i++) { float d = v[i] - mean; s2 += d * d; }
    float inv = rsqrtf(blockReduceSum(s2) * (1.f / DIMC) + 1e-5f);
    bf16* orow = outb + (size_t)row * DIMC;
    #pragma unroll
    for (int i = 0; i < 4; i++) {
        int c = i * 256 + t;
        orow[c] = __float2bfloat16((v[i] - mean) * inv * g[c] + b[c]);
    }
}

/* ---------------- weight fp32 -> bf16 with zero padding -------------------- */
__global__ void convert_pad(const float* __restrict__ src, bf16* __restrict__ dst,
                            int srows, int scols, int dcols, long long total) {
    long long i = (long long)blockIdx.x * 256 + threadIdx.x;
    if (i >= total) return;
    int r = (int)(i / dcols), c = (int)(i % dcols);
    float v = (r < srows && c < scols) ? src[(size_t)r * scols + c] : 0.f;
    dst[i] = __float2bfloat16(v);
}

/* ---------------- qkv split + per-head LN (bf16 out) ----------------------- */
__global__ void qkv_split_norm(const float* __restrict__ f1,
                               const float* __restrict__ qg, const float* __restrict__ qb,
                               const float* __restrict__ kg, const float* __restrict__ kb,
                               bf16* __restrict__ q, bf16* __restrict__ k, bf16* __restrict__ v) {
    int w = blockIdx.x * (blockDim.x >> 5) + (threadIdx.x >> 5);
    int lane = threadIdx.x & 31;
    int tkn = w >> 4, h = w & 15;
    int b = tkn >> 10, n = tkn & 1023;
    const float* row = f1 + (size_t)tkn * F1NP;
    size_t obase = ((size_t)(b * HEADS + h) * SEQ + n) * HD;
    int d0 = lane * 2, d1 = d0 + 1;
    {
        float v0 = row[h * HD + d0], v1 = row[h * HD + d1];
        float s = v0 + v1;
        #pragma unroll
        for (int o = 16; o > 0; o >>= 1) s += __shfl_xor_sync(0xffffffffu, s, o);
        float m = s * (1.f / HD);
        float e0 = v0 - m, e1 = v1 - m;
        float s2 = e0 * e0 + e1 * e1;
        #pragma unroll
        for (int o = 16; o > 0; o >>= 1) s2 += __shfl_xor_sync(0xffffffffu, s2, o);
        float inv = rsqrtf(s2 * (1.f / HD) + 1e-5f);
        q[obase + d0] = __float2bfloat16(e0 * inv * qg[d0] + qb[d0]);
        q[obase + d1] = __float2bfloat16(e1 * inv * qg[d1] + qb[d1]);
    }
    {
        float v0 = row[DIMC + h * HD + d0], v1 = row[DIMC + h * HD + d1];
        float s = v0 + v1;
        #pragma unroll
        for (int o = 16; o > 0; o >>= 1) s += __shfl_xor_sync(0xffffffffu, s, o);
        float m = s * (1.f / HD);
        float e0 = v0 - m, e1 = v1 - m;
        float s2 = e0 * e0 + e1 * e1;
        #pragma unroll
        for (int o = 16; o > 0; o >>= 1) s2 += __shfl_xor_sync(0xffffffffu, s2, o);
        float inv = rsqrtf(s2 * (1.f / HD) + 1e-5f);
        k[obase + d0] = __float2bfloat16(e0 * inv * kg[d0] + kb[d0]);
        k[obase + d1] = __float2bfloat16(e1 * inv * kg[d1] + kb[d1]);
    }
    v[obase + d0] = __float2bfloat16(row[2 * DIMC + h * HD + d0]);
    v[obase + d1] = __float2bfloat16(row[2 * DIMC + h * HD + d1]);
}

/* ---------------- softmax over bf16 rows (in place) ------------------------ */
__global__ void softmax_rows(bf16* __restrict__ attn) {
    size_t row = blockIdx.x;
    bf16* p = attn + row * SEQ;
    int t = threadIdx.x;
    float v[4]; float mx = -3.0e38f;
    #pragma unroll
    for (int i = 0; i < 4; i++) { v[i] = __bfloat162float(p[i * 256 + t]); mx = fmaxf(mx, v[i]); }
    mx = blockReduceMax(mx);
    float s = 0.f;
    #pragma unroll
    for (int i = 0; i < 4; i++) { v[i] = __expf(v[i] - mx); s += v[i]; }
    s = blockReduceSum(s);
    float inv = 1.f / s;
    #pragma unroll
    for (int i = 0; i < 4; i++) p[i * 256 + t] = __float2bfloat16(v[i] * inv);
}

/* ---------------- exact GELU (padded bf16 out) ----------------------------- */
__global__ void gelu_k(const float* __restrict__ f1, bf16* __restrict__ g) {
    long long i = (long long)blockIdx.x * 256 + threadIdx.x;
    if (i >= (long long)TOK * MLPKP) return;
    int r = (int)(i / MLPKP), c = (int)(i % MLPKP);
    float o = 0.f;
    if (c < MLPH) {
        float x = f1[(size_t)r * F1NP + 3 * DIMC + c];
        o = 0.5f * x * (1.f + erff(x * 0.70710678118654752f));
    }
    g[i] = __float2bfloat16(o);
}

/* ---------------- launcher -------------------------------------------------- */
extern "C" void kernel_launch(void* const* d_in, const int* in_sizes, int n_in,
                              void* d_out, int out_size) {
    const float* x      = (const float*)d_in[0];
    const float* norm_g = (const float*)d_in[1];
    const float* norm_b = (const float*)d_in[2];
    const float* W1     = (const float*)d_in[3];
    const float* b1     = (const float*)d_in[4];
    const float* qn_g   = (const float*)d_in[5];
    const float* qn_b   = (const float*)d_in[6];
    const float* kn_g   = (const float*)d_in[7];
    const float* kn_b   = (const float*)d_in[8];
    const float* projW  = (const float*)d_in[9];
    const float* projb  = (const float*)d_in[10];
    const float* mlpW   = (const float*)d_in[11];
    const float* W2     = (const float*)d_in[12];
    const float* b2     = (const float*)d_in[13];
    const float* ls_g   = (const float*)d_in[14];
    float* out = (float*)d_out;

    unsigned char* base = 0;
    cudaGetSymbolAddress((void**)&base, g_scratch);

    bf16*  p_normx = (bf16*)(base + OF_NORMX);
    bf16*  p_W1b   = (bf16*)(base + OF_W1B);
    bf16*  p_projWb= (bf16*)(base + OF_PROJW);
    bf16*  p_mlpWb = (bf16*)(base + OF_MLPW);
    bf16*  p_W2b   = (bf16*)(base + OF_W2B);
    float* p_f1    = (float*)(base + OF_F1);
    bf16*  p_q     = (bf16*)(base + OF_Q);
    bf16*  p_k     = (bf16*)(base + OF_K);
    bf16*  p_v     = (bf16*)(base + OF_V);
    bf16*  p_attn  = (bf16*)(base + OF_ATTN);
    bf16*  p_xo    = (bf16*)(base + OF_XO);
    bf16*  p_gelu  = (bf16*)(base + OF_GELU);
    bf16*  p_comb  = (bf16*)(base + OF_COMB);

    /* weight conversions (bf16, padded) */
    convert_pad<<<(int)(((long long)DIMC * F1NP + 255) / 256), 256>>>(
        W1, p_W1b, DIMC, F1N, F1NP, (long long)DIMC * F1NP);
    convert_pad<<<(int)(((long long)DIMC * DIMC + 255) / 256), 256>>>(
        projW, p_projWb, DIMC, DIMC, DIMC, (long long)DIMC * DIMC);
    convert_pad<<<(int)(((long long)MLPKP * DIMC + 255) / 256), 256>>>(
        mlpW, p_mlpWb, MLPH, DIMC, DIMC, (long long)MLPKP * DIMC);
    convert_pad<<<(int)(((long long)2 * DIMC * DIMC + 255) / 256), 256>>>(
        W2, p_W2b, 2 * DIMC, DIMC, DIMC, (long long)2 * DIMC * DIMC);

    /* 1. layernorm -> bf16 */
    ln_rows<<<TOK, 256>>>(x, norm_g, norm_b, p_normx);

    /* 2. f1 = normx @ W1 + b1  [4096 x 3840 x 1024], fp32 out */
    hgemm<0, 1, 128><<<dim3(F1NP / 128, TOK / 128, 1), 256>>>(
        p_normx, p_W1b, p_f1, DIMC, DIMC, F1NP, F1NP,
        0, 0, 0, 0, 1, b1, F1N, 0, 0, 1.f);

    /* 3. split + qk layernorm -> bf16 q/k/v */
    qkv_split_norm<<<TOK * HEADS / 8, 256>>>(p_f1, qn_g, qn_b, kn_g, kn_b, p_q, p_k, p_v);

    /* 4. S = 0.125 * q @ k^T  (batched over 64 bh), bf16 out */
    hgemm<1, 0, 128><<<dim3(SEQ / 128, SEQ / 128, BH), 256>>>(
        p_q, p_k, p_attn, HD, HD, HD, SEQ,
        (size_t)SEQ * HD, (size_t)SEQ * HD, (size_t)SEQ * SEQ, 0, 1,
        0, 0, 0, 0, 0.125f);

    /* 5. softmax */
    softmax_rows<<<BH * SEQ, 256>>>(p_attn);

    /* 6. xo = P @ v, token-major bf16 */
    hgemm<1, 1, 64><<<dim3(1, SEQ / 128, BH), 256>>>(
        p_attn, p_v, p_xo, SEQ, SEQ, HD, DIMC,
        (size_t)SEQ * SEQ, (size_t)SEQ * HD, (size_t)SEQ * DIMC, (size_t)HD, HEADS,
        0, 0, 0, 0, 1.f);

    /* 7. gelu -> bf16 padded */
    gelu_k<<<(int)(((long long)TOK * MLPKP + 255) / 256), 256>>>(p_f1, p_gelu);

    /* 8. attn_out = xo @ projW + projb -> comb[:, :1024] bf16 */
    hgemm<1, 1, 128><<<dim3(DIMC / 128, TOK / 128, 1), 256>>>(
        p_xo, p_projWb, p_comb, DIMC, DIMC, DIMC, 2 * DIMC,
        0, 0, 0, 0, 1, projb, DIMC, 0, 0, 1.f);

    /* 9. mlp_out = gelu @ mlpW -> comb[:, 1024:] bf16 */
    hgemm<1, 1, 128><<<dim3(DIMC / 128, TOK / 128, 1), 256>>>(
        p_gelu, p_mlpWb, p_comb + DIMC, MLPKP, MLPKP, DIMC, 2 * DIMC,
        0, 0, 0, 0, 1, 0, 0, 0, 0, 1.f);

    /* 10. out = x + (comb @ W2 + b2) * ls_g  fp32 */
    hgemm<2, 1, 128><<<dim3(DIMC / 128, TOK / 128, 1), 256>>>(
        p_comb, p_W2b, out, 2 * DIMC, 2 * DIMC, DIMC, DIMC,
        0, 0, 0, 0, 1, b2, DIMC, x, ls_g, 1.f);
}

// round 4
// speedup vs baseline: 6.3995x; 1.4635x over previous
#include <cuda_runtime.h>
#include <cuda_bf16.h>
#include <math.h>
#include <stdint.h>

#define DIMC   1024
#define HEADS  16
#define HD     64
#define MLPH   716
#define F1N    3788
#define F1NP   3840
#define MLPKP  736
#define BATCH  4
#define SEQ    1024
#define TOK    (BATCH*SEQ)
#define BH     (BATCH*HEADS)

typedef __nv_bfloat16 bf16;

/* ---------------- single scratch arena ------------------------------------- */
#define SZ_NORMX ((size_t)TOK*DIMC*2)
#define SZ_W1B   ((size_t)DIMC*F1NP*2)
#define SZ_PROJW ((size_t)DIMC*DIMC*2)
#define SZ_MLPW  ((size_t)MLPKP*DIMC*2)
#define SZ_W2B   ((size_t)2*DIMC*DIMC*2)
#define SZ_F1    ((size_t)TOK*F1NP*4)
#define SZ_QKV   ((size_t)BH*SEQ*HD*2)
#define SZ_XO    ((size_t)TOK*DIMC*2)
#define SZ_GELU  ((size_t)TOK*MLPKP*2)
#define SZ_COMB  ((size_t)TOK*2*DIMC*2)

#define OF_NORMX ((size_t)0)
#define OF_W1B   (OF_NORMX + SZ_NORMX)
#define OF_PROJW (OF_W1B   + SZ_W1B)
#define OF_MLPW  (OF_PROJW + SZ_PROJW)
#define OF_W2B   (OF_MLPW  + SZ_MLPW)
#define OF_F1    (OF_W2B   + SZ_W2B)
#define OF_Q     (OF_F1    + SZ_F1)
#define OF_K     (OF_Q     + SZ_QKV)
#define OF_V     (OF_K     + SZ_QKV)
#define OF_XO    (OF_V     + SZ_QKV)
#define OF_GELU  (OF_XO    + SZ_XO)
#define OF_COMB  (OF_GELU  + SZ_GELU)
#define OF_END   (OF_COMB  + SZ_COMB)

__device__ __align__(256) unsigned char g_scratch[OF_END];

/* ---------------- PTX helpers ---------------------------------------------- */
__device__ __forceinline__ uint32_t smem_u32(const void* p) {
    return (uint32_t)__cvta_generic_to_shared(p);
}
__device__ __forceinline__ void cp16(uint32_t dst, const void* src) {
    asm volatile("cp.async.cg.shared.global [%0], [%1], 16;\n" :: "r"(dst), "l"(src));
}
__device__ __forceinline__ void cp_commit() { asm volatile("cp.async.commit_group;\n"); }
__device__ __forceinline__ void cp_wait0()  { asm volatile("cp.async.wait_group 0;\n"); }
__device__ __forceinline__ void cp_wait1()  { asm volatile("cp.async.wait_group 1;\n"); }
__device__ __forceinline__ void cp_wait2()  { asm volatile("cp.async.wait_group 2;\n"); }
__device__ __forceinline__ void ldm_x4(uint32_t& r0, uint32_t& r1, uint32_t& r2, uint32_t& r3, uint32_t a) {
    asm volatile("ldmatrix.sync.aligned.m8n8.x4.shared.b16 {%0,%1,%2,%3}, [%4];\n"
                 : "=r"(r0), "=r"(r1), "=r"(r2), "=r"(r3) : "r"(a));
}
__device__ __forceinline__ void ldm_x2(uint32_t& r0, uint32_t& r1, uint32_t a) {
    asm volatile("ldmatrix.sync.aligned.m8n8.x2.shared.b16 {%0,%1}, [%2];\n"
                 : "=r"(r0), "=r"(r1) : "r"(a));
}
__device__ __forceinline__ void ldm_x2_t(uint32_t& r0, uint32_t& r1, uint32_t a) {
    asm volatile("ldmatrix.sync.aligned.m8n8.x2.trans.shared.b16 {%0,%1}, [%2];\n"
                 : "=r"(r0), "=r"(r1) : "r"(a));
}
__device__ __forceinline__ void mma16816(float* c, const uint32_t* a, const uint32_t* b) {
    asm volatile("mma.sync.aligned.m16n8k16.row.col.f32.bf16.bf16.f32 "
                 "{%0,%1,%2,%3}, {%4,%5,%6,%7}, {%8,%9}, {%0,%1,%2,%3};\n"
                 : "+f"(c[0]), "+f"(c[1]), "+f"(c[2]), "+f"(c[3])
                 : "r"(a[0]), "r"(a[1]), "r"(a[2]), "r"(a[3]), "r"(b[0]), "r"(b[1]));
}
__device__ __forceinline__ uint32_t packbf2(float lo, float hi) {
    __nv_bfloat162 p = __floats2bfloat162_rn(lo, hi);
    return *(uint32_t*)&p;
}

/* ---------------- hgemm: 128x128x32 tiles, 3-stage cp.async ----------------
   B row-major [K,N].  EPI 0: f32 C=acc+bias | 1: bf16 C=acc+bias | 2: f32
   C=resid+(acc+bias)*ls.  All dims multiples of 128/32 (buffers padded).    */
#define HG_ASZ  (128*40)
#define HG_BSS  136
#define HG_BSZ  (32*HG_BSS)
#define HG_SMEM ((3*(HG_ASZ + HG_BSZ))*2)

__device__ __forceinline__ void hg_prefetch(
        const bf16* __restrict__ A, const bf16* __restrict__ B,
        bf16* As, bf16* Bs, int k0, int bm, int bn, int lda, int ldb, int t) {
    int ar = t >> 1, ac = (t & 1) * 16;
    uint32_t ad = smem_u32(As + ar * 40 + ac);
    const bf16* asrc = A + (size_t)(bm + ar) * lda + k0 + ac;
    cp16(ad, asrc);
    cp16(ad + 16, asrc + 8);
    int br = t >> 3, bc = (t & 7) * 16;
    uint32_t bd = smem_u32(Bs + br * HG_BSS + bc);
    const bf16* bsrc = B + (size_t)(k0 + br) * ldb + bn + bc;
    cp16(bd, bsrc);
    cp16(bd + 16, bsrc + 8);
}

template<int EPI>
__global__ __launch_bounds__(256) void hgemm(
        const bf16* __restrict__ A, const bf16* __restrict__ B, void* __restrict__ Cv,
        int K, int lda, int ldb, int ldc,
        const float* __restrict__ bias, int nbias,
        const float* __restrict__ resid, const float* __restrict__ ls) {
    extern __shared__ __align__(16) bf16 sm[];
    bf16* As = sm;
    bf16* Bs = sm + 3 * HG_ASZ;

    const int t = threadIdx.x;
    const int lane = t & 31, warp = t >> 5;
    const int bm = blockIdx.y * 128;
    const int bn = blockIdx.x * 128;
    const int wm = (warp >> 2) * 64;     /* 2 warps M x 4 warps N */
    const int wn = (warp & 3) * 32;

    float acc[4][4][4];
    #pragma unroll
    for (int i = 0; i < 4; i++)
        #pragma unroll
        for (int j = 0; j < 4; j++)
            #pragma unroll
            for (int e = 0; e < 4; e++) acc[i][j][e] = 0.f;

    const int KT = K / 32;

    hg_prefetch(A, B, As, Bs, 0, bm, bn, lda, ldb, t);
    cp_commit();
    if (KT > 1) hg_prefetch(A, B, As + HG_ASZ, Bs + HG_BSZ, 32, bm, bn, lda, ldb, t);
    cp_commit();

    for (int kt = 0; kt < KT; kt++) {
        if (kt + 2 < KT) {
            int st = (kt + 2) % 3;
            hg_prefetch(A, B, As + st * HG_ASZ, Bs + st * HG_BSZ, (kt + 2) * 32, bm, bn, lda, ldb, t);
        }
        cp_commit();
        cp_wait2();
        __syncthreads();

        int s = kt % 3;
        bf16* as = As + s * HG_ASZ;
        bf16* bs = Bs + s * HG_BSZ;
        #pragma unroll
        for (int kk = 0; kk < 2; kk++) {
            uint32_t afr[4][4];
            #pragma unroll
            for (int i = 0; i < 4; i++) {
                uint32_t a = smem_u32(as + (wm + i * 16 + (lane & 15)) * 40 + kk * 16 + (lane >> 4) * 8);
                ldm_x4(afr[i][0], afr[i][1], afr[i][2], afr[i][3], a);
            }
            uint32_t bfr[4][2];
            #pragma unroll
            for (int j = 0; j < 4; j++) {
                uint32_t a = smem_u32(bs + (kk * 16 + (lane & 15)) * HG_BSS + wn + j * 8);
                ldm_x2_t(bfr[j][0], bfr[j][1], a);
            }
            #pragma unroll
            for (int i = 0; i < 4; i++)
                #pragma unroll
                for (int j = 0; j < 4; j++)
                    mma16816(acc[i][j], afr[i], bfr[j]);
        }
        __syncthreads();
    }

    #pragma unroll
    for (int i = 0; i < 4; i++) {
        int m0 = bm + wm + i * 16 + (lane >> 2);
        #pragma unroll
        for (int j = 0; j < 4; j++) {
            int n0 = bn + wn + j * 8 + (lane & 3) * 2;
            #pragma unroll
            for (int e = 0; e < 4; e++) {
                int m = m0 + (e >> 1) * 8;
                int n = n0 + (e & 1);
                float v = acc[i][j][e];
                float bv = (bias != 0 && n < nbias) ? bias[n] : 0.f;
                if (EPI == 0) {
                    ((float*)Cv)[(size_t)m * ldc + n] = v + bv;
                } else if (EPI == 1) {
                    ((bf16*)Cv)[(size_t)m * ldc + n] = __float2bfloat16(v + bv);
                } else {
                    ((float*)Cv)[(size_t)m * ldc + n] =
                        resid[(size_t)m * ldc + n] + (v + bv) * ls[n];
                }
            }
        }
    }
}

/* ---------------- flash attention ------------------------------------------
   grid (SEQ/128, BH), 256 threads (8 warps x 16 q-rows).
   Streams K/V in 128-key chunks, double buffered. O written token-major.    */
#define FA_LDS  72
#define FA_TSZ  (128*FA_LDS)
#define FA_SMEM ((5*FA_TSZ)*2)

__device__ __forceinline__ void fa_load_tile(const bf16* __restrict__ src, bf16* dst, int t) {
    #pragma unroll
    for (int i = 0; i < 4; i++) {
        int idx = t + i * 256;              /* 0..1023 */
        int r = idx >> 3, c = (idx & 7) * 8;
        cp16(smem_u32(dst + r * FA_LDS + c), src + (size_t)r * HD + c);
    }
}

__global__ __launch_bounds__(256, 1) void fattn(
        const bf16* __restrict__ q, const bf16* __restrict__ k,
        const bf16* __restrict__ v, bf16* __restrict__ xo) {
    extern __shared__ __align__(16) bf16 fsm[];
    bf16* Qs = fsm;                 /* 128 x 72 */
    bf16* Ks = fsm + FA_TSZ;        /* 2 stages */
    bf16* Vs = fsm + 3 * FA_TSZ;    /* 2 stages */

    const int t = threadIdx.x;
    const int lane = t & 31, w = t >> 5;
    const int bh = blockIdx.y;
    const int q0 = blockIdx.x * 128;
    const bf16* qp = q + ((size_t)bh * SEQ + q0) * HD;
    const bf16* kp = k + (size_t)bh * SEQ * HD;
    const bf16* vp = v + (size_t)bh * SEQ * HD;

    /* Q -> smem -> fragments */
    fa_load_tile(qp, Qs, t);
    cp_commit();
    cp_wait0();
    __syncthreads();
    uint32_t qf[4][4];
    #pragma unroll
    for (int kk = 0; kk < 4; kk++) {
        uint32_t a = smem_u32(Qs + (w * 16 + (lane & 15)) * FA_LDS + kk * 16 + (lane >> 4) * 8);
        ldm_x4(qf[kk][0], qf[kk][1], qf[kk][2], qf[kk][3], a);
    }

    float oacc[8][4];
    #pragma unroll
    for (int jn = 0; jn < 8; jn++)
        #pragma unroll
        for (int e = 0; e < 4; e++) oacc[jn][e] = 0.f;
    float m0r = -1e30f, m1r = -1e30f, l0 = 0.f, l1 = 0.f;

    fa_load_tile(kp, Ks, t);
    fa_load_tile(vp, Vs, t);
    cp_commit();

    for (int c = 0; c < SEQ / 128; c++) {
        if (c + 1 < SEQ / 128) {
            int sn = (c + 1) & 1;
            fa_load_tile(kp + (size_t)(c + 1) * 128 * HD, Ks + sn * FA_TSZ, t);
            fa_load_tile(vp + (size_t)(c + 1) * 128 * HD, Vs + sn * FA_TSZ, t);
        }
        cp_commit();
        cp_wait1();
        __syncthreads();

        const int s = c & 1;
        bf16* ks = Ks + s * FA_TSZ;
        bf16* vs = Vs + s * FA_TSZ;

        /* S = Q @ K^T, 16 x 128 per warp */
        float sacc[16][4];
        #pragma unroll
        for (int j = 0; j < 16; j++)
            #pragma unroll
            for (int e = 0; e < 4; e++) sacc[j][e] = 0.f;
        #pragma unroll
        for (int kk = 0; kk < 4; kk++) {
            #pragma unroll
            for (int j = 0; j < 16; j++) {
                uint32_t b0, b1;
                ldm_x2(b0, b1, smem_u32(ks + (j * 8 + (lane & 7)) * FA_LDS + kk * 16 + ((lane >> 3) & 1) * 8));
                uint32_t bb[2] = {b0, b1};
                mma16816(sacc[j], qf[kk], bb);
            }
        }
        #pragma unroll
        for (int j = 0; j < 16; j++)
            #pragma unroll
            for (int e = 0; e < 4; e++) sacc[j][e] *= 0.125f;

        /* online softmax (rows rA=lane>>2, rB=rA+8) */
        float mx0 = -1e30f, mx1 = -1e30f;
        #pragma unroll
        for (int j = 0; j < 16; j++) {
            mx0 = fmaxf(mx0, fmaxf(sacc[j][0], sacc[j][1]));
            mx1 = fmaxf(mx1, fmaxf(sacc[j][2], sacc[j][3]));
        }
        mx0 = fmaxf(mx0, __shfl_xor_sync(0xffffffffu, mx0, 1));
        mx0 = fmaxf(mx0, __shfl_xor_sync(0xffffffffu, mx0, 2));
        mx1 = fmaxf(mx1, __shfl_xor_sync(0xffffffffu, mx1, 1));
        mx1 = fmaxf(mx1, __shfl_xor_sync(0xffffffffu, mx1, 2));
        float mn0 = fmaxf(m0r, mx0), mn1 = fmaxf(m1r, mx1);
        float al0 = __expf(m0r - mn0), al1 = __expf(m1r - mn1);
        m0r = mn0; m1r = mn1;

        float sum0 = 0.f, sum1 = 0.f;
        #pragma unroll
        for (int j = 0; j < 16; j++) {
            sacc[j][0] = __expf(sacc[j][0] - mn0);
            sacc[j][1] = __expf(sacc[j][1] - mn0);
            sacc[j][2] = __expf(sacc[j][2] - mn1);
            sacc[j][3] = __expf(sacc[j][3] - mn1);
            sum0 += sacc[j][0] + sacc[j][1];
            sum1 += sacc[j][2] + sacc[j][3];
        }
        sum0 += __shfl_xor_sync(0xffffffffu, sum0, 1);
        sum0 += __shfl_xor_sync(0xffffffffu, sum0, 2);
        sum1 += __shfl_xor_sync(0xffffffffu, sum1, 1);
        sum1 += __shfl_xor_sync(0xffffffffu, sum1, 2);
        l0 = l0 * al0 + sum0;
        l1 = l1 * al1 + sum1;
        #pragma unroll
        for (int jn = 0; jn < 8; jn++) {
            oacc[jn][0] *= al0; oacc[jn][1] *= al0;
            oacc[jn][2] *= al1; oacc[jn][3] *= al1;
        }

        /* P (bf16 A-fragments) @ V */
        uint32_t pa[8][4];
        #pragma unroll
        for (int jp = 0; jp < 8; jp++) {
            pa[jp][0] = packbf2(sacc[2 * jp][0],     sacc[2 * jp][1]);
            pa[jp][1] = packbf2(sacc[2 * jp][2],     sacc[2 * jp][3]);
            pa[jp][2] = packbf2(sacc[2 * jp + 1][0], sacc[2 * jp + 1][1]);
            pa[jp][3] = packbf2(sacc[2 * jp + 1][2], sacc[2 * jp + 1][3]);
        }
        #pragma unroll
        for (int jp = 0; jp < 8; jp++) {
            #pragma unroll
            for (int jn = 0; jn < 8; jn++) {
                uint32_t b0, b1;
                ldm_x2_t(b0, b1, smem_u32(vs + (jp * 16 + (lane & 15)) * FA_LDS + jn * 8));
                uint32_t bb[2] = {b0, b1};
                mma16816(oacc[jn], pa[jp], bb);
            }
        }
        __syncthreads();
    }

    /* epilogue: O /= l, token-major bf16 */
    float inv0 = 1.f / l0, inv1 = 1.f / l1;
    int b = bh / HEADS, h = bh % HEADS;
    int rA = lane >> 2;
    int tok0 = b * SEQ + q0 + w * 16 + rA;
    int colb = h * HD + (lane & 3) * 2;
    #pragma unroll
    for (int jn = 0; jn < 8; jn++) {
        __nv_bfloat162 v0 = __floats2bfloat162_rn(oacc[jn][0] * inv0, oacc[jn][1] * inv0);
        __nv_bfloat162 v1 = __floats2bfloat162_rn(oacc[jn][2] * inv1, oacc[jn][3] * inv1);
        *(__nv_bfloat162*)(xo + (size_t)tok0 * DIMC + colb + jn * 8) = v0;
        *(__nv_bfloat162*)(xo + (size_t)(tok0 + 8) * DIMC + colb + jn * 8) = v1;
    }
}

/* ---------------- reductions ------------------------------------------------ */
__device__ __forceinline__ float blockReduceSum(float val) {
    __shared__ float sh[32];
    int lane = threadIdx.x & 31, wid = threadIdx.x >> 5;
    #pragma unroll
    for (int o = 16; o > 0; o >>= 1) val += __shfl_down_sync(0xffffffffu, val, o);
    if (lane == 0) sh[wid] = val;
    __syncthreads();
    val = (threadIdx.x < (blockDim.x >> 5)) ? sh[threadIdx.x] : 0.f;
    if (wid == 0) {
        #pragma unroll
        for (int o = 16; o > 0; o >>= 1) val += __shfl_down_sync(0xffffffffu, val, o);
        if (lane == 0) sh[0] = val;
    }
    __syncthreads();
    float r = sh[0];
    __syncthreads();
    return r;
}

/* ---------------- LayerNorm -> bf16 ---------------------------------------- */
__global__ void ln_rows(const float* __restrict__ x, const float* __restrict__ g,
                        const float* __restrict__ b, bf16* __restrict__ outb) {
    int row = blockIdx.x, t = threadIdx.x;
    const float* xr = x + (size_t)row * DIMC;
    float v[4]; float s = 0.f;
    #pragma unroll
    for (int i = 0; i < 4; i++) { v[i] = xr[i * 256 + t]; s += v[i]; }
    float mean = blockReduceSum(s) * (1.f / DIMC);
    float s2 = 0.f;
    #pragma unroll
    for (int i = 0; i < 4; i++) { float d = v[i] - mean; s2 += d * d; }
    float inv = rsqrtf(blockReduceSum(s2) * (1.f / DIMC) + 1e-5f);
    bf16* orow = outb + (size_t)row * DIMC;
    #pragma unroll
    for (int i = 0; i < 4; i++) {
        int c = i * 256 + t;
        orow[c] = __float2bfloat16((v[i] - mean) * inv * g[c] + b[c]);
    }
}

/* ---------------- weight fp32 -> bf16 with zero padding -------------------- */
__global__ void convert_pad(const float* __restrict__ src, bf16* __restrict__ dst,
                            int srows, int scols, int dcols, long long total) {
    long long i = (long long)blockIdx.x * 256 + threadIdx.x;
    if (i >= total) return;
    int r = (int)(i / dcols), c = (int)(i % dcols);
    float v = (r < srows && c < scols) ? src[(size_t)r * scols + c] : 0.f;
    dst[i] = __float2bfloat16(v);
}

/* ---------------- qkv split + per-head LN (bf16 out) ----------------------- */
__global__ void qkv_split_norm(const float* __restrict__ f1,
                               const float* __restrict__ qg, const float* __restrict__ qb,
                               const float* __restrict__ kg, const float* __restrict__ kb,
                               bf16* __restrict__ q, bf16* __restrict__ k, bf16* __restrict__ v) {
    int w = blockIdx.x * (blockDim.x >> 5) + (threadIdx.x >> 5);
    int lane = threadIdx.x & 31;
    int tkn = w >> 4, h = w & 15;
    int b = tkn >> 10, n = tkn & 1023;
    const float* row = f1 + (size_t)tkn * F1NP;
    size_t obase = ((size_t)(b * HEADS + h) * SEQ + n) * HD;
    int d0 = lane * 2, d1 = d0 + 1;
    {
        float v0 = row[h * HD + d0], v1 = row[h * HD + d1];
        float s = v0 + v1;
        #pragma unroll
        for (int o = 16; o > 0; o >>= 1) s += __shfl_xor_sync(0xffffffffu, s, o);
        float m = s * (1.f / HD);
        float e0 = v0 - m, e1 = v1 - m;
        float s2 = e0 * e0 + e1 * e1;
        #pragma unroll
        for (int o = 16; o > 0; o >>= 1) s2 += __shfl_xor_sync(0xffffffffu, s2, o);
        float inv = rsqrtf(s2 * (1.f / HD) + 1e-5f);
        q[obase + d0] = __float2bfloat16(e0 * inv * qg[d0] + qb[d0]);
        q[obase + d1] = __float2bfloat16(e1 * inv * qg[d1] + qb[d1]);
    }
    {
        float v0 = row[DIMC + h * HD + d0], v1 = row[DIMC + h * HD + d1];
        float s = v0 + v1;
        #pragma unroll
        for (int o = 16; o > 0; o >>= 1) s += __shfl_xor_sync(0xffffffffu, s, o);
        float m = s * (1.f / HD);
        float e0 = v0 - m, e1 = v1 - m;
        float s2 = e0 * e0 + e1 * e1;
        #pragma unroll
        for (int o = 16; o > 0; o >>= 1) s2 += __shfl_xor_sync(0xffffffffu, s2, o);
        float inv = rsqrtf(s2 * (1.f / HD) + 1e-5f);
        k[obase + d0] = __float2bfloat16(e0 * inv * kg[d0] + kb[d0]);
        k[obase + d1] = __float2bfloat16(e1 * inv * kg[d1] + kb[d1]);
    }
    v[obase + d0] = __float2bfloat16(row[2 * DIMC + h * HD + d0]);
    v[obase + d1] = __float2bfloat16(row[2 * DIMC + h * HD + d1]);
}

/* ---------------- exact GELU (padded bf16 out) ----------------------------- */
__global__ void gelu_k(const float* __restrict__ f1, bf16* __restrict__ g) {
    long long i = (long long)blockIdx.x * 256 + threadIdx.x;
    if (i >= (long long)TOK * MLPKP) return;
    int r = (int)(i / MLPKP), c = (int)(i % MLPKP);
    float o = 0.f;
    if (c < MLPH) {
        float x = f1[(size_t)r * F1NP + 3 * DIMC + c];
        o = 0.5f * x * (1.f + erff(x * 0.70710678118654752f));
    }
    g[i] = __float2bfloat16(o);
}

/* ---------------- launcher -------------------------------------------------- */
extern "C" void kernel_launch(void* const* d_in, const int* in_sizes, int n_in,
                              void* d_out, int out_size) {
    const float* x      = (const float*)d_in[0];
    const float* norm_g = (const float*)d_in[1];
    const float* norm_b = (const float*)d_in[2];
    const float* W1     = (const float*)d_in[3];
    const float* b1     = (const float*)d_in[4];
    const float* qn_g   = (const float*)d_in[5];
    const float* qn_b   = (const float*)d_in[6];
    const float* kn_g   = (const float*)d_in[7];
    const float* kn_b   = (const float*)d_in[8];
    const float* projW  = (const float*)d_in[9];
    const float* projb  = (const float*)d_in[10];
    const float* mlpW   = (const float*)d_in[11];
    const float* W2     = (const float*)d_in[12];
    const float* b2     = (const float*)d_in[13];
    const float* ls_g   = (const float*)d_in[14];
    float* out = (float*)d_out;

    unsigned char* base = 0;
    cudaGetSymbolAddress((void**)&base, g_scratch);

    bf16*  p_normx = (bf16*)(base + OF_NORMX);
    bf16*  p_W1b   = (bf16*)(base + OF_W1B);
    bf16*  p_projWb= (bf16*)(base + OF_PROJW);
    bf16*  p_mlpWb = (bf16*)(base + OF_MLPW);
    bf16*  p_W2b   = (bf16*)(base + OF_W2B);
    float* p_f1    = (float*)(base + OF_F1);
    bf16*  p_q     = (bf16*)(base + OF_Q);
    bf16*  p_k     = (bf16*)(base + OF_K);
    bf16*  p_v     = (bf16*)(base + OF_V);
    bf16*  p_xo    = (bf16*)(base + OF_XO);
    bf16*  p_gelu  = (bf16*)(base + OF_GELU);
    bf16*  p_comb  = (bf16*)(base + OF_COMB);

    static int attr_done = 0;
    if (!attr_done) {
        cudaFuncSetAttribute(hgemm<0>, cudaFuncAttributeMaxDynamicSharedMemorySize, HG_SMEM);
        cudaFuncSetAttribute(hgemm<1>, cudaFuncAttributeMaxDynamicSharedMemorySize, HG_SMEM);
        cudaFuncSetAttribute(hgemm<2>, cudaFuncAttributeMaxDynamicSharedMemorySize, HG_SMEM);
        cudaFuncSetAttribute(fattn,    cudaFuncAttributeMaxDynamicSharedMemorySize, FA_SMEM);
        attr_done = 1;
    }

    /* weight conversions (bf16, padded) */
    convert_pad<<<(int)(((long long)DIMC * F1NP + 255) / 256), 256>>>(
        W1, p_W1b, DIMC, F1N, F1NP, (long long)DIMC * F1NP);
    convert_pad<<<(int)(((long long)DIMC * DIMC + 255) / 256), 256>>>(
        projW, p_projWb, DIMC, DIMC, DIMC, (long long)DIMC * DIMC);
    convert_pad<<<(int)(((long long)MLPKP * DIMC + 255) / 256), 256>>>(
        mlpW, p_mlpWb, MLPH, DIMC, DIMC, (long long)MLPKP * DIMC);
    convert_pad<<<(int)(((long long)2 * DIMC * DIMC + 255) / 256), 256>>>(
        W2, p_W2b, 2 * DIMC, DIMC, DIMC, (long long)2 * DIMC * DIMC);

    /* 1. layernorm -> bf16 */
    ln_rows<<<TOK, 256>>>(x, norm_g, norm_b, p_normx);

    /* 2. f1 = normx @ W1 + b1  [4096 x 3840 x 1024], fp32 out */
    hgemm<0><<<dim3(F1NP / 128, TOK / 128), 256, HG_SMEM>>>(
        p_normx, p_W1b, p_f1, DIMC, DIMC, F1NP, F1NP, b1, F1N, 0, 0);

    /* 3. split + qk layernorm -> bf16 q/k/v */
    qkv_split_norm<<<TOK * HEADS / 8, 256>>>(p_f1, qn_g, qn_b, kn_g, kn_b, p_q, p_k, p_v);

    /* 4. fused flash attention -> xo (token-major bf16) */
    fattn<<<dim3(SEQ / 128, BH), 256, FA_SMEM>>>(p_q, p_k, p_v, p_xo);

    /* 5. gelu -> bf16 padded */
    gelu_k<<<(int)(((long long)TOK * MLPKP + 255) / 256), 256>>>(p_f1, p_gelu);

    /* 6. attn_out = xo @ projW + projb -> comb[:, :1024] bf16 */
    hgemm<1><<<dim3(DIMC / 128, TOK / 128), 256, HG_SMEM>>>(
        p_xo, p_projWb, p_comb, DIMC, DIMC, DIMC, 2 * DIMC, projb, DIMC, 0, 0);

    /* 7. mlp_out = gelu @ mlpW -> comb[:, 1024:] bf16 */
    hgemm<1><<<dim3(DIMC / 128, TOK / 128), 256, HG_SMEM>>>(
        p_gelu, p_mlpWb, p_comb + DIMC, MLPKP, MLPKP, DIMC, 2 * DIMC, 0, 0, 0, 0);

    /* 8. out = x + (comb @ W2 + b2) * ls_g  fp32 */
    hgemm<2><<<dim3(DIMC / 128, TOK / 128), 256, HG_SMEM>>>(
        p_comb, p_W2b, out, 2 * DIMC, 2 * DIMC, DIMC, DIMC, b2, DIMC, x, ls_g);
}